// round 6
// baseline (speedup 1.0000x reference)
#include <cuda_runtime.h>
#include <cuda_bf16.h>
#include <math.h>
#include <stdint.h>

// Problem constants
#define BATCH 32
#define NNODE 1024
#define FEAT  256           // IN_F == OUT_F == 256
#define MROWS (BATCH*NNODE) // 32768
#define ALPHA_LRELU 0.2f

// ---------------- scratch (device globals; no runtime allocation) -----------
__device__ float g_Wh[(size_t)MROWS * FEAT];                 // 32 MB (tf32-rounded)
__device__ float g_hr[(size_t)MROWS * FEAT];                 // 32 MB tf32(h)
__device__ float g_Wr[FEAT * FEAT];                          // tf32(W)
__device__ float g_si[MROWS];
__device__ float g_sj[MROWS];

// ---------------- helpers ----------------------------------------------------
__device__ __forceinline__ float to_tf32(float x) {
    float r;
    asm("cvt.rna.tf32.f32 %0, %1;" : "=f"(r) : "f"(x));
    return r;
}

__device__ __forceinline__ void cp16(uint32_t dst, const void* src) {
    asm volatile("cp.async.cg.shared.global [%0], [%1], 16;\n" :: "r"(dst), "l"(src));
}
__device__ __forceinline__ void cp_commit() {
    asm volatile("cp.async.commit_group;\n" ::);
}
__device__ __forceinline__ void cp_wait1() {
    asm volatile("cp.async.wait_group 1;\n" ::);
}
__device__ __forceinline__ void cp_wait0() {
    asm volatile("cp.async.wait_group 0;\n" ::);
}

__device__ __forceinline__ void mma_tf32(float* c, const uint32_t* a, const uint32_t* b) {
    asm volatile(
        "mma.sync.aligned.m16n8k8.row.col.f32.tf32.tf32.f32 "
        "{%0,%1,%2,%3}, {%4,%5,%6,%7}, {%8,%9}, {%0,%1,%2,%3};"
        : "+f"(c[0]), "+f"(c[1]), "+f"(c[2]), "+f"(c[3])
        : "r"(a[0]), "r"(a[1]), "r"(a[2]), "r"(a[3]), "r"(b[0]), "r"(b[1]));
}

// ============================================================================
// K0: pre-round h and W to tf32 (rna) so downstream MMA needs no converts.
// ============================================================================
__global__ __launch_bounds__(256) void k_pre(const float* __restrict__ h,
                                             const float* __restrict__ W)
{
    int i = blockIdx.x * 256 + threadIdx.x;             // float4 index
    float4 v = ((const float4*)h)[i];
    v.x = to_tf32(v.x); v.y = to_tf32(v.y);
    v.z = to_tf32(v.z); v.w = to_tf32(v.w);
    ((float4*)g_hr)[i] = v;
    if (i < FEAT * FEAT / 4) {
        float4 w = ((const float4*)W)[i];
        w.x = to_tf32(w.x); w.y = to_tf32(w.y);
        w.z = to_tf32(w.z); w.w = to_tf32(w.w);
        ((float4*)g_Wr)[i] = w;
    }
}

// ============================================================================
// K1: Wh[m,o] = sum_k hr[m,k] * Wr[o,k]   (NT GEMM, M=32768, N=256, K=256)
// Inputs pre-rounded -> raw bits into mma (HW truncation is identity).
// 128x128 CTA tile, BK=16, double-buffered cp.async.
// Epilogue stores tf32(rna)-rounded values into g_Wh.
// ============================================================================
__global__ __launch_bounds__(256, 2) void k_wh_tc()
{
    __shared__ float sA[2][128][20];
    __shared__ float sW[2][128][20];

    const float* A  = g_hr;
    const float* Bw = g_Wr;

    const int m0 = blockIdx.y * 128;
    const int n0 = blockIdx.x * 128;
    const int tid  = threadIdx.x;
    const int lane = tid & 31;
    const int wid  = tid >> 5;
    const int m0w  = (wid >> 2) * 64;   // 0 or 64
    const int n0w  = (wid & 3) * 32;    // 0,32,64,96

    float acc[4][4][4];
#pragma unroll
    for (int i = 0; i < 4; i++)
#pragma unroll
        for (int j = 0; j < 4; j++)
#pragma unroll
            for (int r = 0; r < 4; r++) acc[i][j][r] = 0.f;

    const int T = FEAT / 16;  // 16

    auto load_stage = [&](int buf, int k0) {
#pragma unroll
        for (int it = 0; it < 2; it++) {
            int f   = tid + it * 256;    // 0..511
            int row = f >> 2;
            int kq  = (f & 3) * 4;
            cp16((uint32_t)__cvta_generic_to_shared(&sA[buf][row][kq]),
                 A + (size_t)(m0 + row) * FEAT + k0 + kq);
            cp16((uint32_t)__cvta_generic_to_shared(&sW[buf][row][kq]),
                 Bw + (size_t)(n0 + row) * FEAT + k0 + kq);
        }
    };

    load_stage(0, 0);
    cp_commit();

    for (int t = 0; t < T; t++) {
        if (t + 1 < T) { load_stage((t + 1) & 1, (t + 1) * 16); cp_commit(); }
        if (t + 1 < T) cp_wait1(); else cp_wait0();
        __syncthreads();

        const int buf = t & 1;
#pragma unroll
        for (int kk = 0; kk < 16; kk += 8) {
            uint32_t a[4][4];
#pragma unroll
            for (int mi = 0; mi < 4; mi++) {
                int r = m0w + mi * 16 + (lane >> 2);
                a[mi][0] = __float_as_uint(sA[buf][r    ][kk + (lane & 3)    ]);
                a[mi][1] = __float_as_uint(sA[buf][r + 8][kk + (lane & 3)    ]);
                a[mi][2] = __float_as_uint(sA[buf][r    ][kk + (lane & 3) + 4]);
                a[mi][3] = __float_as_uint(sA[buf][r + 8][kk + (lane & 3) + 4]);
            }
            uint32_t bf[4][2];
#pragma unroll
            for (int nj = 0; nj < 4; nj++) {
                int c = n0w + nj * 8 + (lane >> 2);
                bf[nj][0] = __float_as_uint(sW[buf][c][kk + (lane & 3)    ]);
                bf[nj][1] = __float_as_uint(sW[buf][c][kk + (lane & 3) + 4]);
            }
#pragma unroll
            for (int mi = 0; mi < 4; mi++)
#pragma unroll
                for (int nj = 0; nj < 4; nj++)
                    mma_tf32(acc[mi][nj], a[mi], bf[nj]);
        }
        __syncthreads();
    }

#pragma unroll
    for (int mi = 0; mi < 4; mi++) {
#pragma unroll
        for (int nj = 0; nj < 4; nj++) {
            int row = m0 + m0w + mi * 16 + (lane >> 2);
            int col = n0 + n0w + nj * 8 + 2 * (lane & 3);
            float2 v0 = make_float2(to_tf32(acc[mi][nj][0]), to_tf32(acc[mi][nj][1]));
            float2 v1 = make_float2(to_tf32(acc[mi][nj][2]), to_tf32(acc[mi][nj][3]));
            *(float2*)(g_Wh + (size_t)row * FEAT + col)       = v0;
            *(float2*)(g_Wh + (size_t)(row + 8) * FEAT + col) = v1;
        }
    }
}

// ============================================================================
// K2: si = Wh @ a1, sj = Wh @ a2  (one warp per row)
// ============================================================================
__global__ __launch_bounds__(256) void k_sisj(const float* __restrict__ a)
{
    int row  = blockIdx.x * 8 + (threadIdx.x >> 5);
    int lane = threadIdx.x & 31;
    const float* w = g_Wh + (size_t)row * FEAT;
    float d1 = 0.f, d2 = 0.f;
#pragma unroll
    for (int u = 0; u < 8; u++) {
        int k = lane + u * 32;
        float v = w[k];
        d1 += v * a[k];
        d2 += v * a[FEAT + k];
    }
#pragma unroll
    for (int s = 16; s > 0; s >>= 1) {
        d1 += __shfl_xor_sync(0xffffffff, d1, s);
        d2 += __shfl_xor_sync(0xffffffff, d2, s);
    }
    if (lane == 0) { g_si[row] = d1; g_sj[row] = d2; }
}

// ============================================================================
// K3 (fused, pipelined): for each 128-row i-tile of batch b:
//   E[i,j] = adj>0 ? exp(leaky_relu(si[i]+sj[j])) : 0
//   O[i,:] = (E @ Wh[b]) / rowsum(E), then ELU.
// BI=128, BJ=32, 512 threads (16 warps: 4m x 4n, warp tile 32x64), 1 CTA/SM.
// Single __syncthreads per j-step; E double-buffered; cp.async distance-1.
// ============================================================================
#define BI 128
#define BJ 32

struct SmemFused {
    float wh[2][BJ][264];    // [k][n] B tiles
    float e[2][BI][36];      // E tiles, double-buffered
    int   adj[2][BI][BJ];
    float sj[NNODE];
    float rs[BI];
};

__global__ __launch_bounds__(512, 1) void k_fused(const int* __restrict__ adj,
                                                  float* __restrict__ out)
{
    extern __shared__ char smem_raw[];
    SmemFused* s = (SmemFused*)smem_raw;

    const int b  = blockIdx.y;
    const int i0 = blockIdx.x * BI;
    const int tid  = threadIdx.x;
    const int lane = tid & 31;
    const int wid  = tid >> 5;
    const int m0w  = (wid >> 2) * 32;   // 0,32,64,96
    const int n0w  = (wid & 3) * 64;    // 0,64,128,192

    const int*   adjb = adj  + ((size_t)b * NNODE + i0) * NNODE;
    const float* Whb  = g_Wh + (size_t)b * NNODE * FEAT;

    // preload sj for this batch (1024 floats, 2/thread) + per-thread si
    {
        float2 v = *(const float2*)(g_sj + (size_t)b * NNODE + tid * 2);
        *(float2*)&s->sj[tid * 2] = v;
    }
    const int   erow = tid >> 2;            // E row this thread produces (0..127)
    const int   ecol = (tid & 3) * 8;       // first of 8 E cols
    const float si_r = g_si[(size_t)b * NNODE + i0 + erow];

    float acc[2][8][4];
#pragma unroll
    for (int i = 0; i < 2; i++)
#pragma unroll
        for (int j = 0; j < 8; j++)
#pragma unroll
            for (int r = 0; r < 4; r++) acc[i][j][r] = 0.f;

    float esum = 0.f;

    auto load_adj = [&](int buf, int j0) {
#pragma unroll
        for (int it = 0; it < 2; it++) {
            int f   = tid + it * 512;          // 0..1023
            int row = f >> 3;
            int c   = (f & 7) * 4;
            cp16((uint32_t)__cvta_generic_to_shared(&s->adj[buf][row][c]),
                 adjb + (size_t)row * NNODE + j0 + c);
        }
    };
    auto load_wh = [&](int buf, int j0) {
#pragma unroll
        for (int it = 0; it < 4; it++) {
            int f = tid + it * 512;            // 0..2047
            int k = f >> 6;
            int c = (f & 63) * 4;
            cp16((uint32_t)__cvta_generic_to_shared(&s->wh[buf][k][c]),
                 Whb + (size_t)(j0 + k) * FEAT + c);
        }
    };

    const int T = NNODE / BJ;  // 32

    // Preamble: G_a = {adj(0)}, G_0 = {wh(0), adj(1)}
    load_adj(0, 0);
    cp_commit();
    load_wh(0, 0);
    load_adj(1, BJ);
    cp_commit();
    cp_wait1();          // adj(0) arrived
    __syncthreads();

    // E(0) -> e[0]
    {
        float ev[8];
#pragma unroll
        for (int u = 0; u < 8; u++) {
            int jc = ecol + u;
            float x = si_r + s->sj[jc];
            x = (x >= 0.f) ? x : ALPHA_LRELU * x;
            float e = (s->adj[0][erow][jc] > 0) ? __expf(x) : 0.f;
            e = to_tf32(e);
            esum += e;
            ev[u] = e;
        }
        *(float4*)&s->e[0][erow][ecol]     = make_float4(ev[0], ev[1], ev[2], ev[3]);
        *(float4*)&s->e[0][erow][ecol + 4] = make_float4(ev[4], ev[5], ev[6], ev[7]);
    }
    __syncthreads();

    for (int t = 0; t < T; t++) {
        const int buf = t & 1;

        // Commit G_{t+1} = {wh(t+1), adj(t+2)}
        if (t + 1 < T) {
            load_wh(buf ^ 1, (t + 1) * BJ);
            if (t + 2 < T) load_adj(buf, (t + 2) * BJ);
            cp_commit();
            cp_wait1();        // G_t arrived: wh(t) + adj(t+1)
        } else {
            cp_wait0();
        }

        // ---- MMA(t): 128x256 += E(t) @ Wh(t) ----
#pragma unroll
        for (int kk = 0; kk < BJ; kk += 8) {
            uint32_t a[2][4];
#pragma unroll
            for (int mi = 0; mi < 2; mi++) {
                int r = m0w + mi * 16 + (lane >> 2);
                a[mi][0] = __float_as_uint(s->e[buf][r    ][kk + (lane & 3)    ]);
                a[mi][1] = __float_as_uint(s->e[buf][r + 8][kk + (lane & 3)    ]);
                a[mi][2] = __float_as_uint(s->e[buf][r    ][kk + (lane & 3) + 4]);
                a[mi][3] = __float_as_uint(s->e[buf][r + 8][kk + (lane & 3) + 4]);
            }
            uint32_t bf[8][2];
#pragma unroll
            for (int nj = 0; nj < 8; nj++) {
                int c = n0w + nj * 8 + (lane >> 2);
                bf[nj][0] = __float_as_uint(s->wh[buf][kk + (lane & 3)    ][c]);
                bf[nj][1] = __float_as_uint(s->wh[buf][kk + (lane & 3) + 4][c]);
            }
#pragma unroll
            for (int mi = 0; mi < 2; mi++)
#pragma unroll
                for (int nj = 0; nj < 8; nj++)
                    mma_tf32(acc[mi][nj], a[mi], bf[nj]);
        }

        // ---- E-compute(t+1) -> e[buf^1] (overlaps with HMMA drain) ----
        if (t + 1 < T) {
            const int j0 = (t + 1) * BJ;
            float ev[8];
#pragma unroll
            for (int u = 0; u < 8; u++) {
                int jc = ecol + u;
                float x = si_r + s->sj[j0 + jc];
                x = (x >= 0.f) ? x : ALPHA_LRELU * x;
                float e = (s->adj[buf ^ 1][erow][jc] > 0) ? __expf(x) : 0.f;
                e = to_tf32(e);
                esum += e;
                ev[u] = e;
            }
            *(float4*)&s->e[buf ^ 1][erow][ecol]     = make_float4(ev[0], ev[1], ev[2], ev[3]);
            *(float4*)&s->e[buf ^ 1][erow][ecol + 4] = make_float4(ev[4], ev[5], ev[6], ev[7]);
        }

        __syncthreads();   // single barrier per iteration
    }

    // rowsum reduce: 4 threads (same erow) hold partials
    esum += __shfl_xor_sync(0xffffffff, esum, 1);
    esum += __shfl_xor_sync(0xffffffff, esum, 2);
    if ((tid & 3) == 0) s->rs[erow] = esum;
    __syncthreads();

    // epilogue: normalize, ELU, store
#pragma unroll
    for (int mi = 0; mi < 2; mi++) {
        int r0 = m0w + mi * 16 + (lane >> 2);
        float inv0 = 1.f / s->rs[r0];
        float inv1 = 1.f / s->rs[r0 + 8];
#pragma unroll
        for (int nj = 0; nj < 8; nj++) {
            int col = n0w + nj * 8 + 2 * (lane & 3);
            float v0 = acc[mi][nj][0] * inv0, v1 = acc[mi][nj][1] * inv0;
            float v2 = acc[mi][nj][2] * inv1, v3 = acc[mi][nj][3] * inv1;
            v0 = (v0 > 0.f) ? v0 : expm1f(v0);
            v1 = (v1 > 0.f) ? v1 : expm1f(v1);
            v2 = (v2 > 0.f) ? v2 : expm1f(v2);
            v3 = (v3 > 0.f) ? v3 : expm1f(v3);
            size_t base = (size_t)(b * NNODE + i0 + r0) * FEAT + col;
            *(float2*)(out + base)            = make_float2(v0, v1);
            *(float2*)(out + base + 8 * FEAT) = make_float2(v2, v3);
        }
    }
}

// ============================================================================
// launch
// ============================================================================
extern "C" void kernel_launch(void* const* d_in, const int* in_sizes, int n_in,
                              void* d_out, int out_size)
{
    const float* h   = (const float*)d_in[0];
    const int*   adj = (const int*)  d_in[1];
    const float* W   = (const float*)d_in[2];
    const float* a   = (const float*)d_in[3];
    float*       out = (float*)d_out;

    // K0: pre-round h, W to tf32 (rna)
    k_pre<<<(MROWS * FEAT / 4) / 256, 256>>>(h, W);
    // K1: Wh = hr @ Wr^T (tensor cores, tf32, no in-loop cvts)
    {
        dim3 grid(FEAT / 128, MROWS / 128);   // (2, 256)
        k_wh_tc<<<grid, 256>>>();
    }
    // K2: si, sj
    k_sisj<<<MROWS / 8, 256>>>(a);
    // K3: fused masked-softmax + attn@Wh + ELU (pipelined, BI=128)
    {
        cudaFuncSetAttribute(k_fused, cudaFuncAttributeMaxDynamicSharedMemorySize,
                             (int)sizeof(SmemFused));
        dim3 grid(NNODE / BI, BATCH);         // (8, 32)
        k_fused<<<grid, 512, sizeof(SmemFused)>>>(adj, out);
    }
}

// round 7
// speedup vs baseline: 1.1951x; 1.1951x over previous
#include <cuda_runtime.h>
#include <cuda_bf16.h>
#include <math.h>
#include <stdint.h>

// Problem constants
#define BATCH 32
#define NNODE 1024
#define FEAT  256           // IN_F == OUT_F == 256
#define MROWS (BATCH*NNODE) // 32768
#define ALPHA_LRELU 0.2f

// ---------------- scratch (device globals; no runtime allocation) -----------
__device__ float g_Wh[(size_t)MROWS * FEAT];                 // 32 MB (tf32-rounded)
__device__ float g_si[MROWS];
__device__ float g_sj[MROWS];

// ---------------- helpers ----------------------------------------------------
__device__ __forceinline__ float to_tf32(float x) {
    float r;
    asm("cvt.rna.tf32.f32 %0, %1;" : "=f"(r) : "f"(x));
    return r;
}

__device__ __forceinline__ void cp16(uint32_t dst, const void* src) {
    asm volatile("cp.async.cg.shared.global [%0], [%1], 16;\n" :: "r"(dst), "l"(src));
}
__device__ __forceinline__ void cp_commit() {
    asm volatile("cp.async.commit_group;\n" ::);
}
__device__ __forceinline__ void cp_wait1() {
    asm volatile("cp.async.wait_group 1;\n" ::);
}
__device__ __forceinline__ void cp_wait0() {
    asm volatile("cp.async.wait_group 0;\n" ::);
}

__device__ __forceinline__ void mma_tf32(float* c, const uint32_t* a, const uint32_t* b) {
    asm volatile(
        "mma.sync.aligned.m16n8k8.row.col.f32.tf32.tf32.f32 "
        "{%0,%1,%2,%3}, {%4,%5,%6,%7}, {%8,%9}, {%0,%1,%2,%3};"
        : "+f"(c[0]), "+f"(c[1]), "+f"(c[2]), "+f"(c[3])
        : "r"(a[0]), "r"(a[1]), "r"(a[2]), "r"(a[3]), "r"(b[0]), "r"(b[1]));
}

// ============================================================================
// K1: Wh[m,o] = sum_k h[m,k] * W[o,k]   (NT GEMM, M=32768, N=256, K=256)
// tf32 mma with rna cvt on fragments (proven numerics), 128x128 tile, BK=16.
// ============================================================================
__global__ __launch_bounds__(256, 2) void k_wh_tc(const float* __restrict__ A,
                                                  const float* __restrict__ Bw)
{
    __shared__ float sA[2][128][20];
    __shared__ float sW[2][128][20];

    const int m0 = blockIdx.y * 128;
    const int n0 = blockIdx.x * 128;
    const int tid  = threadIdx.x;
    const int lane = tid & 31;
    const int wid  = tid >> 5;
    const int m0w  = (wid >> 2) * 64;   // 0 or 64
    const int n0w  = (wid & 3) * 32;    // 0,32,64,96

    float acc[4][4][4];
#pragma unroll
    for (int i = 0; i < 4; i++)
#pragma unroll
        for (int j = 0; j < 4; j++)
#pragma unroll
            for (int r = 0; r < 4; r++) acc[i][j][r] = 0.f;

    const int T = FEAT / 16;  // 16

    auto load_stage = [&](int buf, int k0) {
#pragma unroll
        for (int it = 0; it < 2; it++) {
            int f   = tid + it * 256;    // 0..511
            int row = f >> 2;
            int kq  = (f & 3) * 4;
            cp16((uint32_t)__cvta_generic_to_shared(&sA[buf][row][kq]),
                 A + (size_t)(m0 + row) * FEAT + k0 + kq);
            cp16((uint32_t)__cvta_generic_to_shared(&sW[buf][row][kq]),
                 Bw + (size_t)(n0 + row) * FEAT + k0 + kq);
        }
    };

    load_stage(0, 0);
    cp_commit();

    for (int t = 0; t < T; t++) {
        if (t + 1 < T) { load_stage((t + 1) & 1, (t + 1) * 16); cp_commit(); }
        if (t + 1 < T) cp_wait1(); else cp_wait0();
        __syncthreads();

        const int buf = t & 1;
#pragma unroll
        for (int kk = 0; kk < 16; kk += 8) {
            uint32_t a[4][4];
#pragma unroll
            for (int mi = 0; mi < 4; mi++) {
                int r = m0w + mi * 16 + (lane >> 2);
                a[mi][0] = __float_as_uint(to_tf32(sA[buf][r    ][kk + (lane & 3)    ]));
                a[mi][1] = __float_as_uint(to_tf32(sA[buf][r + 8][kk + (lane & 3)    ]));
                a[mi][2] = __float_as_uint(to_tf32(sA[buf][r    ][kk + (lane & 3) + 4]));
                a[mi][3] = __float_as_uint(to_tf32(sA[buf][r + 8][kk + (lane & 3) + 4]));
            }
            uint32_t bf[4][2];
#pragma unroll
            for (int nj = 0; nj < 4; nj++) {
                int c = n0w + nj * 8 + (lane >> 2);
                bf[nj][0] = __float_as_uint(to_tf32(sW[buf][c][kk + (lane & 3)    ]));
                bf[nj][1] = __float_as_uint(to_tf32(sW[buf][c][kk + (lane & 3) + 4]));
            }
#pragma unroll
            for (int mi = 0; mi < 4; mi++)
#pragma unroll
                for (int nj = 0; nj < 4; nj++)
                    mma_tf32(acc[mi][nj], a[mi], bf[nj]);
        }
        __syncthreads();
    }

#pragma unroll
    for (int mi = 0; mi < 4; mi++) {
#pragma unroll
        for (int nj = 0; nj < 4; nj++) {
            int row = m0 + m0w + mi * 16 + (lane >> 2);
            int col = n0 + n0w + nj * 8 + 2 * (lane & 3);
            float2 v0 = make_float2(to_tf32(acc[mi][nj][0]), to_tf32(acc[mi][nj][1]));
            float2 v1 = make_float2(to_tf32(acc[mi][nj][2]), to_tf32(acc[mi][nj][3]));
            *(float2*)(g_Wh + (size_t)row * FEAT + col)       = v0;
            *(float2*)(g_Wh + (size_t)(row + 8) * FEAT + col) = v1;
        }
    }
}

// ============================================================================
// K2: si = Wh @ a1, sj = Wh @ a2  (one warp per row)
// ============================================================================
__global__ __launch_bounds__(256) void k_sisj(const float* __restrict__ a)
{
    int row  = blockIdx.x * 8 + (threadIdx.x >> 5);
    int lane = threadIdx.x & 31;
    const float* w = g_Wh + (size_t)row * FEAT;
    float d1 = 0.f, d2 = 0.f;
#pragma unroll
    for (int u = 0; u < 8; u++) {
        int k = lane + u * 32;
        float v = w[k];
        d1 += v * a[k];
        d2 += v * a[FEAT + k];
    }
#pragma unroll
    for (int s = 16; s > 0; s >>= 1) {
        d1 += __shfl_xor_sync(0xffffffff, d1, s);
        d2 += __shfl_xor_sync(0xffffffff, d2, s);
    }
    if (lane == 0) { g_si[row] = d1; g_sj[row] = d2; }
}

// ============================================================================
// K3 (fused, pipelined, factorized-exp): per 64-row i-tile of batch b:
//   E[i,j] = adj ? ( pi*pj >= 1 ? pi*pj : qi*qj ) : 0
//     with pi=exp(si), qi=exp(0.2 si), pj=exp(sj), qj=exp(0.2 sj).
//   (exp(lrelu(si+sj)) factorizes because lrelu is piecewise linear;
//    pi*pj>=1 <=> si+sj>=0 by monotonicity.)
//   O[i,:] = (E @ Wh[b]) / rowsum(E), then ELU.
// E truncated to tf32 via bitmask; rowsum uses the SAME truncated values, so
// truncation bias cancels in the normalization.
// BI=64, BJ=32, 256 threads, 2 CTAs/SM. One __syncthreads per j-step.
// ============================================================================
#define BI 64
#define BJ 32

struct SmemFused {
    float wh[2][BJ][264];    // [k][n] B tiles
    float e[2][BI][36];      // E tiles, double-buffered
    int   adj[2][BI][BJ];
    float pj[NNODE];         // exp(sj)
    float qj[NNODE];         // exp(0.2 sj)
    float rs[BI];
};

__global__ __launch_bounds__(256, 2) void k_fused(const int* __restrict__ adj,
                                                  float* __restrict__ out)
{
    extern __shared__ char smem_raw[];
    SmemFused* s = (SmemFused*)smem_raw;

    const int b  = blockIdx.y;
    const int i0 = blockIdx.x * BI;
    const int tid  = threadIdx.x;
    const int lane = tid & 31;
    const int wid  = tid >> 5;
    const int m0w  = (wid >> 2) * 32;   // 0 or 32
    const int n0w  = (wid & 3) * 64;    // 0,64,128,192

    const int*   adjb = adj  + ((size_t)b * NNODE + i0) * NNODE;
    const float* Whb  = g_Wh + (size_t)b * NNODE * FEAT;

    // preamble: pj/qj for this batch (4 per thread), pi/qi for this row
#pragma unroll
    for (int u = 0; u < 4; u++) {
        int j = tid + u * 256;
        float sjv = g_sj[(size_t)b * NNODE + j];
        s->pj[j] = __expf(sjv);
        s->qj[j] = __expf(ALPHA_LRELU * sjv);
    }
    const int   erow = tid >> 2;            // E row this thread produces
    const int   ecol = (tid & 3) * 8;       // first of 8 E cols
    const float si_r = g_si[(size_t)b * NNODE + i0 + erow];
    const float pi_r = __expf(si_r);
    const float qi_r = __expf(ALPHA_LRELU * si_r);

    float acc[2][8][4];
#pragma unroll
    for (int i = 0; i < 2; i++)
#pragma unroll
        for (int j = 0; j < 8; j++)
#pragma unroll
            for (int r = 0; r < 4; r++) acc[i][j][r] = 0.f;

    float esum = 0.f;

    auto load_adj = [&](int buf, int j0) {
#pragma unroll
        for (int it = 0; it < 2; it++) {
            int f   = tid + it * 256;
            int row = f >> 3;
            int c   = (f & 7) * 4;
            cp16((uint32_t)__cvta_generic_to_shared(&s->adj[buf][row][c]),
                 adjb + (size_t)row * NNODE + j0 + c);
        }
    };
    auto load_wh = [&](int buf, int j0) {
#pragma unroll
        for (int it = 0; it < 8; it++) {
            int f = tid + it * 256;
            int k = f >> 6;
            int c = (f & 63) * 4;
            cp16((uint32_t)__cvta_generic_to_shared(&s->wh[buf][k][c]),
                 Whb + (size_t)(j0 + k) * FEAT + c);
        }
    };

    // E-tile compute into e[ebuf] from adj[abuf] at column offset j0
    auto compute_e = [&](int ebuf, int abuf, int j0) {
        float ev[8];
#pragma unroll
        for (int u = 0; u < 8; u++) {
            int jc = ecol + u;
            int jg = j0 + jc;
            float ep = pi_r * s->pj[jg];
            float eq = qi_r * s->qj[jg];
            float e  = (ep >= 1.0f) ? ep : eq;
            e = (s->adj[abuf][erow][jc] > 0) ? e : 0.f;
            e = __uint_as_float(__float_as_uint(e) & 0xffffe000u);  // tf32 trunc
            esum += e;
            ev[u] = e;
        }
        *(float4*)&s->e[ebuf][erow][ecol]     = make_float4(ev[0], ev[1], ev[2], ev[3]);
        *(float4*)&s->e[ebuf][erow][ecol + 4] = make_float4(ev[4], ev[5], ev[6], ev[7]);
    };

    const int T = NNODE / BJ;  // 32

    // Preamble: G_a = {adj(0)}, G_0 = {wh(0), adj(1)}
    load_adj(0, 0);
    cp_commit();
    load_wh(0, 0);
    load_adj(1, BJ);
    cp_commit();
    cp_wait1();          // adj(0) arrived
    __syncthreads();     // also publishes pj/qj

    compute_e(0, 0, 0);
    __syncthreads();

    for (int t = 0; t < T; t++) {
        const int buf = t & 1;

        // Commit G_{t+1} = {wh(t+1), adj(t+2)}
        if (t + 1 < T) {
            load_wh(buf ^ 1, (t + 1) * BJ);
            if (t + 2 < T) load_adj(buf, (t + 2) * BJ);
            cp_commit();
            cp_wait1();        // G_t arrived: wh(t) + adj(t+1)
        } else {
            cp_wait0();
        }

        // ---- MMA(t): 64x256 += E(t) @ Wh(t) ----
#pragma unroll
        for (int kk = 0; kk < BJ; kk += 8) {
            uint32_t a[2][4];
#pragma unroll
            for (int mi = 0; mi < 2; mi++) {
                int r = m0w + mi * 16 + (lane >> 2);
                a[mi][0] = __float_as_uint(s->e[buf][r    ][kk + (lane & 3)    ]);
                a[mi][1] = __float_as_uint(s->e[buf][r + 8][kk + (lane & 3)    ]);
                a[mi][2] = __float_as_uint(s->e[buf][r    ][kk + (lane & 3) + 4]);
                a[mi][3] = __float_as_uint(s->e[buf][r + 8][kk + (lane & 3) + 4]);
            }
            uint32_t bf[8][2];
#pragma unroll
            for (int nj = 0; nj < 8; nj++) {
                int c = n0w + nj * 8 + (lane >> 2);
                bf[nj][0] = __float_as_uint(s->wh[buf][kk + (lane & 3)    ][c]);
                bf[nj][1] = __float_as_uint(s->wh[buf][kk + (lane & 3) + 4][c]);
            }
#pragma unroll
            for (int mi = 0; mi < 2; mi++)
#pragma unroll
                for (int nj = 0; nj < 8; nj++)
                    mma_tf32(acc[mi][nj], a[mi], bf[nj]);
        }

        // ---- E-compute(t+1) -> e[buf^1] (overlaps with HMMA drain) ----
        if (t + 1 < T) compute_e(buf ^ 1, buf ^ 1, (t + 1) * BJ);

        __syncthreads();   // single barrier per iteration
    }

    // rowsum reduce: 4 threads (same erow) hold partials
    esum += __shfl_xor_sync(0xffffffff, esum, 1);
    esum += __shfl_xor_sync(0xffffffff, esum, 2);
    if ((tid & 3) == 0) s->rs[erow] = esum;
    __syncthreads();

    // epilogue: normalize, ELU, store
#pragma unroll
    for (int mi = 0; mi < 2; mi++) {
        int r0 = m0w + mi * 16 + (lane >> 2);
        float inv0 = 1.f / s->rs[r0];
        float inv1 = 1.f / s->rs[r0 + 8];
#pragma unroll
        for (int nj = 0; nj < 8; nj++) {
            int col = n0w + nj * 8 + 2 * (lane & 3);
            float v0 = acc[mi][nj][0] * inv0, v1 = acc[mi][nj][1] * inv0;
            float v2 = acc[mi][nj][2] * inv1, v3 = acc[mi][nj][3] * inv1;
            v0 = (v0 > 0.f) ? v0 : expm1f(v0);
            v1 = (v1 > 0.f) ? v1 : expm1f(v1);
            v2 = (v2 > 0.f) ? v2 : expm1f(v2);
            v3 = (v3 > 0.f) ? v3 : expm1f(v3);
            size_t base = (size_t)(b * NNODE + i0 + r0) * FEAT + col;
            *(float2*)(out + base)            = make_float2(v0, v1);
            *(float2*)(out + base + 8 * FEAT) = make_float2(v2, v3);
        }
    }
}

// ============================================================================
// launch
// ============================================================================
extern "C" void kernel_launch(void* const* d_in, const int* in_sizes, int n_in,
                              void* d_out, int out_size)
{
    const float* h   = (const float*)d_in[0];
    const int*   adj = (const int*)  d_in[1];
    const float* W   = (const float*)d_in[2];
    const float* a   = (const float*)d_in[3];
    float*       out = (float*)d_out;

    // K1: Wh = h @ W^T (tensor cores, tf32)
    {
        dim3 grid(FEAT / 128, MROWS / 128);   // (2, 256)
        k_wh_tc<<<grid, 256>>>(h, W);
    }
    // K2: si, sj
    k_sisj<<<MROWS / 8, 256>>>(a);
    // K3: fused masked-softmax + attn@Wh + ELU (pipelined, factorized exp)
    {
        cudaFuncSetAttribute(k_fused, cudaFuncAttributeMaxDynamicSharedMemorySize,
                             (int)sizeof(SmemFused));
        dim3 grid(NNODE / BI, BATCH);         // (16, 32)
        k_fused<<<grid, 256, sizeof(SmemFused)>>>(adj, out);
    }
}

// round 8
// speedup vs baseline: 1.2278x; 1.0274x over previous
#include <cuda_runtime.h>
#include <cuda_bf16.h>
#include <math.h>
#include <stdint.h>

// Problem constants
#define BATCH 32
#define NNODE 1024
#define FEAT  256           // IN_F == OUT_F == 256
#define MROWS (BATCH*NNODE) // 32768
#define ALPHA_LRELU 0.2f

// ---------------- scratch (device globals; no runtime allocation) -----------
__device__ float g_Wh[(size_t)MROWS * FEAT];                 // 32 MB (tf32-rounded)
__device__ float g_si[MROWS];
__device__ float g_sj[MROWS];

// ---------------- helpers ----------------------------------------------------
__device__ __forceinline__ float to_tf32(float x) {
    float r;
    asm("cvt.rna.tf32.f32 %0, %1;" : "=f"(r) : "f"(x));
    return r;
}

__device__ __forceinline__ void cp16(uint32_t dst, const void* src) {
    asm volatile("cp.async.cg.shared.global [%0], [%1], 16;\n" :: "r"(dst), "l"(src));
}
__device__ __forceinline__ void cp_commit() {
    asm volatile("cp.async.commit_group;\n" ::);
}
__device__ __forceinline__ void cp_wait1() {
    asm volatile("cp.async.wait_group 1;\n" ::);
}
__device__ __forceinline__ void cp_wait0() {
    asm volatile("cp.async.wait_group 0;\n" ::);
}

__device__ __forceinline__ void mma_tf32(float* c, const uint32_t* a, const uint32_t* b) {
    asm volatile(
        "mma.sync.aligned.m16n8k8.row.col.f32.tf32.tf32.f32 "
        "{%0,%1,%2,%3}, {%4,%5,%6,%7}, {%8,%9}, {%0,%1,%2,%3};"
        : "+f"(c[0]), "+f"(c[1]), "+f"(c[2]), "+f"(c[3])
        : "r"(a[0]), "r"(a[1]), "r"(a[2]), "r"(a[3]), "r"(b[0]), "r"(b[1]));
}

// ============================================================================
// K1: Wh[m,o] = sum_k h[m,k] * W[o,k]   (NT GEMM, M=32768, N=256, K=256)
// tf32 mma with rna cvt on fragments (proven numerics), 128x128 tile, BK=16.
// Epilogue additionally accumulates si/sj partials (dot with a1/a2 over this
// CTA's 128 output cols) via quad-reduced atomicAdd — replaces k_sisj.
// ============================================================================
__global__ __launch_bounds__(256, 2) void k_wh_tc(const float* __restrict__ A,
                                                  const float* __restrict__ Bw,
                                                  const float* __restrict__ avec)
{
    __shared__ float sA[2][128][20];
    __shared__ float sW[2][128][20];

    const int m0 = blockIdx.y * 128;
    const int n0 = blockIdx.x * 128;
    const int tid  = threadIdx.x;
    const int lane = tid & 31;
    const int wid  = tid >> 5;
    const int m0w  = (wid >> 2) * 64;   // 0 or 64
    const int n0w  = (wid & 3) * 32;    // 0,32,64,96

    float acc[4][4][4];
#pragma unroll
    for (int i = 0; i < 4; i++)
#pragma unroll
        for (int j = 0; j < 4; j++)
#pragma unroll
            for (int r = 0; r < 4; r++) acc[i][j][r] = 0.f;

    const int T = FEAT / 16;  // 16

    auto load_stage = [&](int buf, int k0) {
#pragma unroll
        for (int it = 0; it < 2; it++) {
            int f   = tid + it * 256;    // 0..511
            int row = f >> 2;
            int kq  = (f & 3) * 4;
            cp16((uint32_t)__cvta_generic_to_shared(&sA[buf][row][kq]),
                 A + (size_t)(m0 + row) * FEAT + k0 + kq);
            cp16((uint32_t)__cvta_generic_to_shared(&sW[buf][row][kq]),
                 Bw + (size_t)(n0 + row) * FEAT + k0 + kq);
        }
    };

    load_stage(0, 0);
    cp_commit();

    for (int t = 0; t < T; t++) {
        if (t + 1 < T) { load_stage((t + 1) & 1, (t + 1) * 16); cp_commit(); }
        if (t + 1 < T) cp_wait1(); else cp_wait0();
        __syncthreads();

        const int buf = t & 1;
#pragma unroll
        for (int kk = 0; kk < 16; kk += 8) {
            uint32_t a[4][4];
#pragma unroll
            for (int mi = 0; mi < 4; mi++) {
                int r = m0w + mi * 16 + (lane >> 2);
                a[mi][0] = __float_as_uint(to_tf32(sA[buf][r    ][kk + (lane & 3)    ]));
                a[mi][1] = __float_as_uint(to_tf32(sA[buf][r + 8][kk + (lane & 3)    ]));
                a[mi][2] = __float_as_uint(to_tf32(sA[buf][r    ][kk + (lane & 3) + 4]));
                a[mi][3] = __float_as_uint(to_tf32(sA[buf][r + 8][kk + (lane & 3) + 4]));
            }
            uint32_t bf[4][2];
#pragma unroll
            for (int nj = 0; nj < 4; nj++) {
                int c = n0w + nj * 8 + (lane >> 2);
                bf[nj][0] = __float_as_uint(to_tf32(sW[buf][c][kk + (lane & 3)    ]));
                bf[nj][1] = __float_as_uint(to_tf32(sW[buf][c][kk + (lane & 3) + 4]));
            }
#pragma unroll
            for (int mi = 0; mi < 4; mi++)
#pragma unroll
                for (int nj = 0; nj < 4; nj++)
                    mma_tf32(acc[mi][nj], a[mi], bf[nj]);
        }
        __syncthreads();
    }

    // preload a1/a2 for this thread's 8 columns
    float a1v[8], a2v[8];
#pragma unroll
    for (int nj = 0; nj < 4; nj++) {
        int c = n0 + n0w + nj * 8 + 2 * (lane & 3);
        a1v[nj * 2]     = avec[c];
        a1v[nj * 2 + 1] = avec[c + 1];
        a2v[nj * 2]     = avec[FEAT + c];
        a2v[nj * 2 + 1] = avec[FEAT + c + 1];
    }

#pragma unroll
    for (int mi = 0; mi < 4; mi++) {
        int row = m0 + m0w + mi * 16 + (lane >> 2);
        float p1_lo = 0.f, p2_lo = 0.f, p1_hi = 0.f, p2_hi = 0.f;
#pragma unroll
        for (int nj = 0; nj < 4; nj++) {
            int col = n0 + n0w + nj * 8 + 2 * (lane & 3);
            float v0 = to_tf32(acc[mi][nj][0]);
            float v1 = to_tf32(acc[mi][nj][1]);
            float v2 = to_tf32(acc[mi][nj][2]);
            float v3 = to_tf32(acc[mi][nj][3]);
            *(float2*)(g_Wh + (size_t)row * FEAT + col)       = make_float2(v0, v1);
            *(float2*)(g_Wh + (size_t)(row + 8) * FEAT + col) = make_float2(v2, v3);
            p1_lo += v0 * a1v[nj * 2] + v1 * a1v[nj * 2 + 1];
            p2_lo += v0 * a2v[nj * 2] + v1 * a2v[nj * 2 + 1];
            p1_hi += v2 * a1v[nj * 2] + v3 * a1v[nj * 2 + 1];
            p2_hi += v2 * a2v[nj * 2] + v3 * a2v[nj * 2 + 1];
        }
        // quad reduce (lanes sharing the same rows, different col pairs)
        p1_lo += __shfl_xor_sync(0xffffffff, p1_lo, 1);
        p1_lo += __shfl_xor_sync(0xffffffff, p1_lo, 2);
        p2_lo += __shfl_xor_sync(0xffffffff, p2_lo, 1);
        p2_lo += __shfl_xor_sync(0xffffffff, p2_lo, 2);
        p1_hi += __shfl_xor_sync(0xffffffff, p1_hi, 1);
        p1_hi += __shfl_xor_sync(0xffffffff, p1_hi, 2);
        p2_hi += __shfl_xor_sync(0xffffffff, p2_hi, 1);
        p2_hi += __shfl_xor_sync(0xffffffff, p2_hi, 2);
        if ((lane & 3) == 0) {
            atomicAdd(&g_si[row], p1_lo);
            atomicAdd(&g_sj[row], p2_lo);
            atomicAdd(&g_si[row + 8], p1_hi);
            atomicAdd(&g_sj[row + 8], p2_hi);
        }
    }
}

// ============================================================================
// K3 (fused, pipelined, factorized-exp): per 64-row i-tile of batch b:
//   E[i,j] = adj ? ( pi*pj >= 1 ? pi*pj : qi*qj ) : 0
//   O[i,:] = (E @ Wh[b]) / rowsum(E), then ELU.
// BI=64, BJ=32, 256 threads, 2 CTAs/SM. One __syncthreads per j-step.
// ============================================================================
#define BI 64
#define BJ 32

struct SmemFused {
    float  wh[2][BJ][264];   // [k][n] B tiles
    float  e[2][BI][36];     // E tiles, double-buffered
    int    adj[2][BI][BJ];
    float2 pq[NNODE];        // {exp(sj), exp(0.2 sj)}
    float  rs[BI];
};

__global__ __launch_bounds__(256, 2) void k_fused(const int* __restrict__ adj,
                                                  float* __restrict__ out)
{
    extern __shared__ char smem_raw[];
    SmemFused* s = (SmemFused*)smem_raw;

    const int b  = blockIdx.y;
    const int i0 = blockIdx.x * BI;
    const int tid  = threadIdx.x;
    const int lane = tid & 31;
    const int wid  = tid >> 5;
    const int m0w  = (wid >> 2) * 32;   // 0 or 32
    const int n0w  = (wid & 3) * 64;    // 0,64,128,192

    const int*   adjb = adj  + ((size_t)b * NNODE + i0) * NNODE;
    const float* Whb  = g_Wh + (size_t)b * NNODE * FEAT;

    // preamble: pj/qj for this batch (4 per thread), pi/qi for this row
#pragma unroll
    for (int u = 0; u < 4; u++) {
        int j = tid + u * 256;
        float sjv = g_sj[(size_t)b * NNODE + j];
        s->pq[j] = make_float2(__expf(sjv), __expf(ALPHA_LRELU * sjv));
    }
    const int   erow = tid >> 2;            // E row this thread produces
    const int   ecol = (tid & 3) * 8;       // first of 8 E cols
    const float si_r = g_si[(size_t)b * NNODE + i0 + erow];
    const float pi_r = __expf(si_r);
    const float qi_r = __expf(ALPHA_LRELU * si_r);

    float acc[2][8][4];
#pragma unroll
    for (int i = 0; i < 2; i++)
#pragma unroll
        for (int j = 0; j < 8; j++)
#pragma unroll
            for (int r = 0; r < 4; r++) acc[i][j][r] = 0.f;

    float esum = 0.f;

    auto load_adj = [&](int buf, int j0) {
#pragma unroll
        for (int it = 0; it < 2; it++) {
            int f   = tid + it * 256;
            int row = f >> 3;
            int c   = (f & 7) * 4;
            cp16((uint32_t)__cvta_generic_to_shared(&s->adj[buf][row][c]),
                 adjb + (size_t)row * NNODE + j0 + c);
        }
    };
    auto load_wh = [&](int buf, int j0) {
#pragma unroll
        for (int it = 0; it < 8; it++) {
            int f = tid + it * 256;
            int k = f >> 6;
            int c = (f & 63) * 4;
            cp16((uint32_t)__cvta_generic_to_shared(&s->wh[buf][k][c]),
                 Whb + (size_t)(j0 + k) * FEAT + c);
        }
    };

    // E-tile compute into e[ebuf] from adj[abuf] at column offset j0
    auto compute_e = [&](int ebuf, int abuf, int j0) {
        float ev[8];
#pragma unroll
        for (int u = 0; u < 8; u++) {
            int jc = ecol + u;
            float2 pq = s->pq[j0 + jc];
            float ep = pi_r * pq.x;
            float eq = qi_r * pq.y;
            float e  = (ep >= 1.0f) ? ep : eq;
            e = (s->adj[abuf][erow][jc] > 0) ? e : 0.f;
            e = __uint_as_float(__float_as_uint(e) & 0xffffe000u);  // tf32 trunc
            esum += e;
            ev[u] = e;
        }
        *(float4*)&s->e[ebuf][erow][ecol]     = make_float4(ev[0], ev[1], ev[2], ev[3]);
        *(float4*)&s->e[ebuf][erow][ecol + 4] = make_float4(ev[4], ev[5], ev[6], ev[7]);
    };

    const int T = NNODE / BJ;  // 32

    // Preamble: G_a = {adj(0)}, G_0 = {wh(0), adj(1)}
    load_adj(0, 0);
    cp_commit();
    load_wh(0, 0);
    load_adj(1, BJ);
    cp_commit();
    cp_wait1();          // adj(0) arrived
    __syncthreads();     // also publishes pq

    compute_e(0, 0, 0);
    __syncthreads();

    for (int t = 0; t < T; t++) {
        const int buf = t & 1;

        // Commit G_{t+1} = {wh(t+1), adj(t+2)}
        if (t + 1 < T) {
            load_wh(buf ^ 1, (t + 1) * BJ);
            if (t + 2 < T) load_adj(buf, (t + 2) * BJ);
            cp_commit();
            cp_wait1();        // G_t arrived: wh(t) + adj(t+1)
        } else {
            cp_wait0();
        }

        // ---- MMA(t): 64x256 += E(t) @ Wh(t) ----
#pragma unroll
        for (int kk = 0; kk < BJ; kk += 8) {
            uint32_t a[2][4];
#pragma unroll
            for (int mi = 0; mi < 2; mi++) {
                int r = m0w + mi * 16 + (lane >> 2);
                a[mi][0] = __float_as_uint(s->e[buf][r    ][kk + (lane & 3)    ]);
                a[mi][1] = __float_as_uint(s->e[buf][r + 8][kk + (lane & 3)    ]);
                a[mi][2] = __float_as_uint(s->e[buf][r    ][kk + (lane & 3) + 4]);
                a[mi][3] = __float_as_uint(s->e[buf][r + 8][kk + (lane & 3) + 4]);
            }
            uint32_t bf[8][2];
#pragma unroll
            for (int nj = 0; nj < 8; nj++) {
                int c = n0w + nj * 8 + (lane >> 2);
                bf[nj][0] = __float_as_uint(s->wh[buf][kk + (lane & 3)    ][c]);
                bf[nj][1] = __float_as_uint(s->wh[buf][kk + (lane & 3) + 4][c]);
            }
#pragma unroll
            for (int mi = 0; mi < 2; mi++)
#pragma unroll
                for (int nj = 0; nj < 8; nj++)
                    mma_tf32(acc[mi][nj], a[mi], bf[nj]);
        }

        // ---- E-compute(t+1) -> e[buf^1] (overlaps with HMMA drain) ----
        if (t + 1 < T) compute_e(buf ^ 1, buf ^ 1, (t + 1) * BJ);

        __syncthreads();   // single barrier per iteration
    }

    // rowsum reduce: 4 threads (same erow) hold partials
    esum += __shfl_xor_sync(0xffffffff, esum, 1);
    esum += __shfl_xor_sync(0xffffffff, esum, 2);
    if ((tid & 3) == 0) s->rs[erow] = esum;
    __syncthreads();

    // epilogue: normalize, ELU (exp-based), store
#pragma unroll
    for (int mi = 0; mi < 2; mi++) {
        int r0 = m0w + mi * 16 + (lane >> 2);
        float inv0 = 1.f / s->rs[r0];
        float inv1 = 1.f / s->rs[r0 + 8];
#pragma unroll
        for (int nj = 0; nj < 8; nj++) {
            int col = n0w + nj * 8 + 2 * (lane & 3);
            float v0 = acc[mi][nj][0] * inv0, v1 = acc[mi][nj][1] * inv0;
            float v2 = acc[mi][nj][2] * inv1, v3 = acc[mi][nj][3] * inv1;
            v0 = (v0 > 0.f) ? v0 : (__expf(v0) - 1.f);
            v1 = (v1 > 0.f) ? v1 : (__expf(v1) - 1.f);
            v2 = (v2 > 0.f) ? v2 : (__expf(v2) - 1.f);
            v3 = (v3 > 0.f) ? v3 : (__expf(v3) - 1.f);
            size_t base = (size_t)(b * NNODE + i0 + r0) * FEAT + col;
            *(float2*)(out + base)            = make_float2(v0, v1);
            *(float2*)(out + base + 8 * FEAT) = make_float2(v2, v3);
        }
    }
}

// ============================================================================
// launch
// ============================================================================
extern "C" void kernel_launch(void* const* d_in, const int* in_sizes, int n_in,
                              void* d_out, int out_size)
{
    const float* h   = (const float*)d_in[0];
    const int*   adj = (const int*)  d_in[1];
    const float* W   = (const float*)d_in[2];
    const float* a   = (const float*)d_in[3];
    float*       out = (float*)d_out;

    // zero si/sj (accumulated by atomics in k_wh_tc epilogue)
    void* p_si = nullptr;
    void* p_sj = nullptr;
    cudaGetSymbolAddress(&p_si, g_si);
    cudaGetSymbolAddress(&p_sj, g_sj);
    cudaMemsetAsync(p_si, 0, MROWS * sizeof(float));
    cudaMemsetAsync(p_sj, 0, MROWS * sizeof(float));

    // K1: Wh = h @ W^T (tensor cores, tf32) + fused si/sj accumulation
    {
        dim3 grid(FEAT / 128, MROWS / 128);   // (2, 256)
        k_wh_tc<<<grid, 256>>>(h, W, a);
    }
    // K3: fused masked-softmax + attn@Wh + ELU (pipelined, factorized exp)
    {
        cudaFuncSetAttribute(k_fused, cudaFuncAttributeMaxDynamicSharedMemorySize,
                             (int)sizeof(SmemFused));
        dim3 grid(NNODE / BI, BATCH);         // (16, 32)
        k_fused<<<grid, 256, sizeof(SmemFused)>>>(adj, out);
    }
}